// round 3
// baseline (speedup 1.0000x reference)
#include <cuda_runtime.h>
#include <cuda_bf16.h>
#include <math_constants.h>
#include <cstdint>

// ---------------------------------------------------------------------------
// Problem constants (fixed shapes from reference setup_inputs)
//   x      : (4, 2048, 2048)  -> M = 8192, K1 = 2048
//   w_fc   : (8192, 2048)     -> hidden N1 = 8192 (K-major)
//   w_proj : (2048, 8192)     -> N2 = 2048, K2 = 8192 (K-major)
//   out    : (8192, 2048) fp32
// ---------------------------------------------------------------------------
#define M_DIM    8192
#define DIM      2048
#define HIDDEN   8192

// Device scratch (allocation-free rule: __device__ globals only)
__device__ __align__(256) float g_wq_fc[(size_t)HIDDEN * DIM];     //  64 MB
__device__ __align__(256) float g_wq_proj[(size_t)DIM * HIDDEN];   //  64 MB
__device__ __align__(256) float g_h[(size_t)M_DIM * HIDDEN];       // 256 MB

// np.linspace(0.4, 1.0, 16) cast to float32
__constant__ float c_shrinks[16] = {
    0.40f, 0.44f, 0.48f, 0.52f, 0.56f, 0.60f, 0.64f, 0.68f,
    0.72f, 0.76f, 0.80f, 0.84f, 0.88f, 0.92f, 0.96f, 1.00f
};

// ---------------------------------------------------------------------------
// Block-wise symmetric int5 MSE quantize-dequantize.
// One warp per 64-element block; each lane owns 2 values.
// ---------------------------------------------------------------------------
__global__ void quant_kernel(const float* __restrict__ W,
                             float* __restrict__ WQ,
                             int total_blocks)
{
    int warp = (blockIdx.x * blockDim.x + threadIdx.x) >> 5;
    int lane = threadIdx.x & 31;
    if (warp >= total_blocks) return;

    size_t base = (size_t)warp * 64;
    float v0 = W[base + lane];
    float v1 = W[base + 32 + lane];

    // amax over the 64-block
    float am = fmaxf(fabsf(v0), fabsf(v1));
    #pragma unroll
    for (int o = 16; o > 0; o >>= 1)
        am = fmaxf(am, __shfl_xor_sync(0xffffffffu, am, o));

    float bscale = fmaxf(am, 1e-8f) / 15.0f;   // QMAX = 15

    float best_err   = CUDART_INF_F;
    float best_scale = bscale;

    #pragma unroll
    for (int i = 0; i < 16; i++) {
        float scale = bscale * c_shrinks[i];
        float q0 = fminf(fmaxf(rintf(v0 / scale), -15.0f), 15.0f);
        float q1 = fminf(fmaxf(rintf(v1 / scale), -15.0f), 15.0f);
        float d0 = q0 * scale - v0;
        float d1 = q1 * scale - v1;
        float e  = d0 * d0 + d1 * d1;
        #pragma unroll
        for (int o = 16; o > 0; o >>= 1)
            e += __shfl_xor_sync(0xffffffffu, e, o);
        if (e < best_err) { best_err = e; best_scale = scale; }
    }

    float q0 = fminf(fmaxf(rintf(v0 / best_scale), -15.0f), 15.0f);
    float q1 = fminf(fmaxf(rintf(v1 / best_scale), -15.0f), 15.0f);
    WQ[base + lane]      = q0 * best_scale;
    WQ[base + 32 + lane] = q1 * best_scale;
}

// ---------------------------------------------------------------------------
// NT GEMM: C[M,N] = A[M,K] * B[N,K]^T   (both operands K-contiguous)
// 128x128 tile, BK=16, 256 threads, 8x8 register microkernel.
// RELUSQ: epilogue c = relu(c)^2 (for GEMM1).
// ---------------------------------------------------------------------------
#define BM 128
#define BN 128
#define BK 16

template<int RELUSQ>
__global__ __launch_bounds__(256, 2)
void gemm_nt(const float* __restrict__ A,
             const float* __restrict__ B,
             float* __restrict__ C,
             int M, int N, int K)
{
    __shared__ __align__(16) float As[BK][BM];
    __shared__ __align__(16) float Bs[BK][BN];

    int tid = threadIdx.x;
    int tx  = tid & 15;          // 0..15  -> N direction (8 cols each)
    int ty  = tid >> 4;          // 0..15  -> M direction (8 rows each)

    int m0 = blockIdx.y * BM;
    int n0 = blockIdx.x * BN;

    const float* Aptr = A + (size_t)m0 * K;
    const float* Bptr = B + (size_t)n0 * K;

    // global-load mapping: 512 float4 per tile per matrix, 2 per thread
    int lr = tid >> 2;                 // row 0..63 (second load: +64)
    int lc = (tid & 3) * 4;            // k-offset {0,4,8,12}

    float acc[8][8];
    #pragma unroll
    for (int i = 0; i < 8; i++)
        #pragma unroll
        for (int j = 0; j < 8; j++)
            acc[i][j] = 0.0f;

    for (int kk = 0; kk < K; kk += BK) {
        float4 a0 = *(const float4*)(Aptr + (size_t)lr        * K + kk + lc);
        float4 a1 = *(const float4*)(Aptr + (size_t)(lr + 64) * K + kk + lc);
        float4 b0 = *(const float4*)(Bptr + (size_t)lr        * K + kk + lc);
        float4 b1 = *(const float4*)(Bptr + (size_t)(lr + 64) * K + kk + lc);

        __syncthreads();   // previous iteration's reads must finish

        As[lc + 0][lr] = a0.x; As[lc + 1][lr] = a0.y;
        As[lc + 2][lr] = a0.z; As[lc + 3][lr] = a0.w;
        As[lc + 0][lr + 64] = a1.x; As[lc + 1][lr + 64] = a1.y;
        As[lc + 2][lr + 64] = a1.z; As[lc + 3][lr + 64] = a1.w;

        Bs[lc + 0][lr] = b0.x; Bs[lc + 1][lr] = b0.y;
        Bs[lc + 2][lr] = b0.z; Bs[lc + 3][lr] = b0.w;
        Bs[lc + 0][lr + 64] = b1.x; Bs[lc + 1][lr + 64] = b1.y;
        Bs[lc + 2][lr + 64] = b1.z; Bs[lc + 3][lr + 64] = b1.w;

        __syncthreads();

        #pragma unroll
        for (int k = 0; k < BK; k++) {
            float4 av0 = *(const float4*)&As[k][ty * 8];
            float4 av1 = *(const float4*)&As[k][ty * 8 + 4];
            float4 bv0 = *(const float4*)&Bs[k][tx * 8];
            float4 bv1 = *(const float4*)&Bs[k][tx * 8 + 4];
            float a[8] = {av0.x, av0.y, av0.z, av0.w, av1.x, av1.y, av1.z, av1.w};
            float b[8] = {bv0.x, bv0.y, bv0.z, bv0.w, bv1.x, bv1.y, bv1.z, bv1.w};
            #pragma unroll
            for (int i = 0; i < 8; i++)
                #pragma unroll
                for (int j = 0; j < 8; j++)
                    acc[i][j] = fmaf(a[i], b[j], acc[i][j]);
        }
    }

    // epilogue
    #pragma unroll
    for (int i = 0; i < 8; i++) {
        size_t row = (size_t)(m0 + ty * 8 + i);
        float* crow = C + row * N + n0 + tx * 8;
        float v[8];
        #pragma unroll
        for (int j = 0; j < 8; j++) {
            float c = acc[i][j];
            if (RELUSQ) {
                float r = fmaxf(c, 0.0f);
                c = r * r;
            }
            v[j] = c;
        }
        *(float4*)(crow + 0) = make_float4(v[0], v[1], v[2], v[3]);
        *(float4*)(crow + 4) = make_float4(v[4], v[5], v[6], v[7]);
    }
}

// ---------------------------------------------------------------------------
extern "C" void kernel_launch(void* const* d_in, const int* in_sizes, int n_in,
                              void* d_out, int out_size)
{
    const float* x      = (const float*)d_in[0];   // 8192 x 2048
    const float* w_fc   = (const float*)d_in[1];   // 8192 x 2048
    const float* w_proj = (const float*)d_in[2];   // 2048 x 8192
    float*       out    = (float*)d_out;           // 8192 x 2048

    static float* wq_fc   = nullptr;
    static float* wq_proj = nullptr;
    static float* hbuf    = nullptr;
    if (!wq_fc) {
        cudaGetSymbolAddress((void**)&wq_fc,   g_wq_fc);
        cudaGetSymbolAddress((void**)&wq_proj, g_wq_proj);
        cudaGetSymbolAddress((void**)&hbuf,    g_h);
    }

    // 1) quantize both weight matrices (one warp / 64-block)
    {
        int blocks_fc   = (HIDDEN * DIM) / 64;   // 262144
        int blocks_proj = (DIM * HIDDEN) / 64;   // 262144
        int threads = 256;
        quant_kernel<<<(blocks_fc   * 32 + threads - 1) / threads, threads>>>(w_fc,   wq_fc,   blocks_fc);
        quant_kernel<<<(blocks_proj * 32 + threads - 1) / threads, threads>>>(w_proj, wq_proj, blocks_proj);
    }

    // 2) H = relu(x @ wq_fc^T)^2        (8192 x 8192)
    {
        dim3 grid(HIDDEN / BN, M_DIM / BM);   // (64, 64)
        gemm_nt<1><<<grid, 256>>>(x, wq_fc, hbuf, M_DIM, HIDDEN, DIM);
    }

    // 3) out = H @ wq_proj^T            (8192 x 2048)
    {
        dim3 grid(DIM / BN, M_DIM / BM);      // (16, 64)
        gemm_nt<0><<<grid, 256>>>(hbuf, wq_proj, out, M_DIM, DIM, HIDDEN);
    }
}

// round 7
// speedup vs baseline: 3.3255x; 3.3255x over previous
#include <cuda_runtime.h>
#include <cuda.h>
#include <cuda_bf16.h>
#include <math_constants.h>
#include <cstdint>

#define M_DIM  8192
#define DIM    2048
#define HIDDEN 8192

// Device scratch (allocation-free rule)
__device__ __align__(1024) __nv_bfloat16 g_xh [(size_t)M_DIM * DIM];
__device__ __align__(1024) __nv_bfloat16 g_xl [(size_t)M_DIM * DIM];
__device__ __align__(1024) __nv_bfloat16 g_wfh[(size_t)HIDDEN * DIM];
__device__ __align__(1024) __nv_bfloat16 g_wfl[(size_t)HIDDEN * DIM];
__device__ __align__(1024) __nv_bfloat16 g_wph[(size_t)DIM * HIDDEN];
__device__ __align__(1024) __nv_bfloat16 g_wpl[(size_t)DIM * HIDDEN];
__device__ __align__(1024) __nv_bfloat16 g_hh [(size_t)M_DIM * HIDDEN];
__device__ __align__(1024) __nv_bfloat16 g_hl [(size_t)M_DIM * HIDDEN];

__constant__ float c_shrinks[16] = {
    0.40f, 0.44f, 0.48f, 0.52f, 0.56f, 0.60f, 0.64f, 0.68f,
    0.72f, 0.76f, 0.80f, 0.84f, 0.88f, 0.92f, 0.96f, 1.00f
};

// ---------------- PTX helpers (baseline ISA only, no tcgen05) ----------------
__device__ __forceinline__ uint32_t smem_u32(const void* p) {
    uint32_t a;
    asm("{ .reg .u64 t; cvta.to.shared.u64 t, %1; cvt.u32.u64 %0, t; }" : "=r"(a) : "l"(p));
    return a;
}
#define MBARRIER_INIT(a, c) \
    asm volatile("mbarrier.init.shared.b64 [%0], %1;" :: "r"(a), "r"(c) : "memory")
#define MBARRIER_EXPECT_TX(a, b) \
    asm volatile("mbarrier.arrive.expect_tx.shared.b64 _, [%0], %1;" :: "r"(a), "r"(b) : "memory")

__device__ __forceinline__ int mbar_try(uint32_t a, uint32_t ph) {
    uint32_t d;
    asm volatile("{\n\t.reg .pred p;\n\t"
        "mbarrier.try_wait.parity.acquire.cta.shared::cta.b64 p, [%1], %2, 0x989680;\n\t"
        "selp.b32 %0, 1, 0, p;\n\t}" : "=r"(d) : "r"(a), "r"(ph) : "memory");
    return d;
}
// Bounded wait: converts a never-arriving barrier into a clean trap, not a hang.
#define MBARRIER_WAIT(a, ph) do { \
    uint32_t _m = (a), _p = (uint32_t)(ph); long _i = 0; \
    while (!mbar_try(_m, _p)) { if (++_i > (1L << 22)) __trap(); } \
} while (0)

#define TMA2D(sm, mp, cx, cy, mb) \
    asm volatile("cp.async.bulk.tensor.2d.shared::cta.global.tile.mbarrier::complete_tx::bytes " \
                 "[%0], [%1, {%2, %3}], [%4];" \
                 :: "r"(sm), "l"(mp), "r"(cx), "r"(cy), "r"(mb) : "memory")

#define LDSM_X4(r0, r1, r2, r3, addr) \
    asm volatile("ldmatrix.sync.aligned.m8n8.x4.shared.b16 {%0,%1,%2,%3}, [%4];" \
        : "=r"(r0), "=r"(r1), "=r"(r2), "=r"(r3) : "r"(addr))

__device__ __forceinline__ void mma_bf16(float* c, const uint32_t* a, const uint32_t* b) {
    asm volatile(
        "mma.sync.aligned.m16n8k16.row.col.f32.bf16.bf16.f32 "
        "{%0,%1,%2,%3}, {%4,%5,%6,%7}, {%8,%9}, {%0,%1,%2,%3};"
        : "+f"(c[0]), "+f"(c[1]), "+f"(c[2]), "+f"(c[3])
        : "r"(a[0]), "r"(a[1]), "r"(a[2]), "r"(a[3]), "r"(b[0]), "r"(b[1]));
}

__device__ __forceinline__ uint32_t sw128(uint32_t off) {
    return off ^ ((off >> 3) & 0x70);
}

// ---------------- prep kernels ----------------
__device__ __forceinline__ void split_bf16(float v, __nv_bfloat16& h, __nv_bfloat16& l) {
    h = __float2bfloat16_rn(v);
    l = __float2bfloat16_rn(v - __bfloat162float(h));
}

__global__ void quant_split_kernel(const float* __restrict__ W,
                                   __nv_bfloat16* __restrict__ WH,
                                   __nv_bfloat16* __restrict__ WL,
                                   int total_blocks)
{
    int warp = (blockIdx.x * blockDim.x + threadIdx.x) >> 5;
    int lane = threadIdx.x & 31;
    if (warp >= total_blocks) return;
    size_t base = (size_t)warp * 64;
    float v0 = W[base + lane];
    float v1 = W[base + 32 + lane];
    float am = fmaxf(fabsf(v0), fabsf(v1));
    #pragma unroll
    for (int o = 16; o > 0; o >>= 1)
        am = fmaxf(am, __shfl_xor_sync(0xffffffffu, am, o));
    float bscale = fmaxf(am, 1e-8f) / 15.0f;
    float best_err = CUDART_INF_F, best_scale = bscale;
    #pragma unroll
    for (int i = 0; i < 16; i++) {
        float scale = bscale * c_shrinks[i];
        float q0 = fminf(fmaxf(rintf(v0 / scale), -15.0f), 15.0f);
        float q1 = fminf(fmaxf(rintf(v1 / scale), -15.0f), 15.0f);
        float d0 = q0 * scale - v0, d1 = q1 * scale - v1;
        float e = d0 * d0 + d1 * d1;
        #pragma unroll
        for (int o = 16; o > 0; o >>= 1)
            e += __shfl_xor_sync(0xffffffffu, e, o);
        if (e < best_err) { best_err = e; best_scale = scale; }
    }
    float q0 = fminf(fmaxf(rintf(v0 / best_scale), -15.0f), 15.0f);
    float q1 = fminf(fmaxf(rintf(v1 / best_scale), -15.0f), 15.0f);
    __nv_bfloat16 h, l;
    split_bf16(q0 * best_scale, h, l); WH[base + lane] = h;      WL[base + lane] = l;
    split_bf16(q1 * best_scale, h, l); WH[base + 32 + lane] = h; WL[base + 32 + lane] = l;
}

__global__ void split_kernel(const float4* __restrict__ in,
                             uint2* __restrict__ hi, uint2* __restrict__ lo, int n4)
{
    int i = blockIdx.x * blockDim.x + threadIdx.x;
    if (i >= n4) return;
    float4 v = in[i];
    __nv_bfloat16 h0, h1, h2, h3, l0, l1, l2, l3;
    split_bf16(v.x, h0, l0); split_bf16(v.y, h1, l1);
    split_bf16(v.z, h2, l2); split_bf16(v.w, h3, l3);
    __nv_bfloat162 ha = __halves2bfloat162(h0, h1), hb = __halves2bfloat162(h2, h3);
    __nv_bfloat162 la = __halves2bfloat162(l0, l1), lb = __halves2bfloat162(l2, l3);
    hi[i] = make_uint2(*(uint32_t*)&ha, *(uint32_t*)&hb);
    lo[i] = make_uint2(*(uint32_t*)&la, *(uint32_t*)&lb);
}

// ---------------- mma.sync GEMM ----------------
// C[M,N] = A[M,K]*B[N,K]^T, bf16 hi/lo planes, 3 MMA passes (AhBh+AhBl+AlBh).
// CTA 128x128, K-chunk 64, 8 warps (2x4), warp tile 64x32.
// 3-stage TMA pipeline, 64KB/stage. MODE1: relusq + bf16-split out; MODE0: fp32.
#define OFF_AH 0
#define OFF_AL 16384
#define OFF_BH 32768
#define OFF_BL 49152
#define STAGE_BYTES 65536
#define NSTAGE 3
#define GSMEM_SZ (2048 + NSTAGE * STAGE_BYTES)

template<int MODE>
__global__ void __launch_bounds__(256, 1) gemm_mma(
    const __grid_constant__ CUtensorMap tAh,
    const __grid_constant__ CUtensorMap tAl,
    const __grid_constant__ CUtensorMap tBh,
    const __grid_constant__ CUtensorMap tBl,
    float* __restrict__ outF,
    __nv_bfloat16* __restrict__ outH,
    __nv_bfloat16* __restrict__ outL,
    int Nst, int K_total)
{
    extern __shared__ char smem_raw[];
    uint32_t sb = smem_u32(smem_raw);
    uint32_t ab = (sb + 1023u) & ~1023u;
    const uint32_t ST0 = ab + 1024;

    int tid  = threadIdx.x;
    int lane = tid & 31;
    int warp = tid >> 5;
    int wm = warp & 1;          // 0..1 -> 64-row slab
    int wn = warp >> 1;         // 0..3 -> 32-col slab
    int m0 = blockIdx.y * 128;
    int n0 = blockIdx.x * 128;

    if (tid == 0) {
        MBARRIER_INIT(ab + 0, 1);
        MBARRIER_INIT(ab + 8, 1);
        MBARRIER_INIT(ab + 16, 1);
    }
    __syncthreads();

    const int NC = K_total / 64;

    // Prologue: fill all 3 stages
    if (tid == 0) {
        #pragma unroll
        for (int c = 0; c < NSTAGE; c++) {
            uint32_t st = ST0 + c * STAGE_BYTES;
            uint32_t mb = ab + c * 8;
            MBARRIER_EXPECT_TX(mb, STAGE_BYTES);
            int k0 = c * 64;
            TMA2D(st + OFF_AH, &tAh, k0, m0, mb);
            TMA2D(st + OFF_AL, &tAl, k0, m0, mb);
            TMA2D(st + OFF_BH, &tBh, k0, n0, mb);
            TMA2D(st + OFF_BL, &tBl, k0, n0, mb);
        }
    }

    // ldmatrix per-lane patterns (non-trans, K-contiguous 128B rows)
    int a_r = (lane < 16) ? lane : (lane - 16);
    int a_k = (lane < 16) ? 0 : 8;
    int g = lane >> 3;
    int b_r = (lane & 7) + ((g & 2) << 2);   // +8 rows for groups 2,3
    int b_k = (g & 1) << 3;                  // +8 k for groups 1,3

    float acc[4][4][4];
    #pragma unroll
    for (int i = 0; i < 4; i++)
        #pragma unroll
        for (int j = 0; j < 4; j++)
            #pragma unroll
            for (int q = 0; q < 4; q++)
                acc[i][j][q] = 0.0f;

    int phase[NSTAGE] = {0, 0, 0};

    for (int c = 0; c < NC; c++) {
        int s = c % NSTAGE;
        MBARRIER_WAIT(ab + s * 8, phase[s]);
        phase[s] ^= 1;
        uint32_t st = ST0 + s * STAGE_BYTES;

        #pragma unroll
        for (int ks = 0; ks < 4; ks++) {
            int k0 = ks * 16;
            uint32_t Ah[4][4], Al[4][4], Bh[2][4], Bl[2][4];
            #pragma unroll
            for (int mi = 0; mi < 4; mi++) {
                uint32_t off = (uint32_t)((wm * 64 + mi * 16 + a_r) * 128 + (k0 + a_k) * 2);
                off = sw128(off);
                LDSM_X4(Ah[mi][0], Ah[mi][1], Ah[mi][2], Ah[mi][3], st + OFF_AH + off);
                LDSM_X4(Al[mi][0], Al[mi][1], Al[mi][2], Al[mi][3], st + OFF_AL + off);
            }
            #pragma unroll
            for (int ni = 0; ni < 2; ni++) {
                uint32_t off = (uint32_t)((wn * 32 + ni * 16 + b_r) * 128 + (k0 + b_k) * 2);
                off = sw128(off);
                LDSM_X4(Bh[ni][0], Bh[ni][1], Bh[ni][2], Bh[ni][3], st + OFF_BH + off);
                LDSM_X4(Bl[ni][0], Bl[ni][1], Bl[ni][2], Bl[ni][3], st + OFF_BL + off);
            }
            #pragma unroll
            for (int mi = 0; mi < 4; mi++) {
                #pragma unroll
                for (int nj = 0; nj < 4; nj++) {
                    const uint32_t* bh = &Bh[nj >> 1][(nj & 1) * 2];
                    const uint32_t* bl = &Bl[nj >> 1][(nj & 1) * 2];
                    mma_bf16(acc[mi][nj], Ah[mi], bh);
                    mma_bf16(acc[mi][nj], Ah[mi], bl);
                    mma_bf16(acc[mi][nj], Al[mi], bh);
                }
            }
        }
        __syncthreads();          // all warps done reading stage s
        if (tid == 0 && c + NSTAGE < NC) {
            uint32_t mb = ab + s * 8;
            MBARRIER_EXPECT_TX(mb, STAGE_BYTES);
            int k0 = (c + NSTAGE) * 64;
            TMA2D(st + OFF_AH, &tAh, k0, m0, mb);
            TMA2D(st + OFF_AL, &tAl, k0, m0, mb);
            TMA2D(st + OFF_BH, &tBh, k0, n0, mb);
            TMA2D(st + OFF_BL, &tBl, k0, n0, mb);
        }
    }

    // Epilogue straight from registers.
    int mbase = m0 + wm * 64 + (lane >> 2);
    int nbase = n0 + wn * 32 + (lane & 3) * 2;
    #pragma unroll
    for (int mi = 0; mi < 4; mi++) {
        #pragma unroll
        for (int nj = 0; nj < 4; nj++) {
            int m = mbase + mi * 16;
            int n = nbase + nj * 8;
            if (MODE == 1) {
                #pragma unroll
                for (int h = 0; h < 2; h++) {      // h=0: row m; h=1: row m+8
                    float v0 = acc[mi][nj][2 * h + 0];
                    float v1 = acc[mi][nj][2 * h + 1];
                    v0 = fmaxf(v0, 0.0f); v0 *= v0;
                    v1 = fmaxf(v1, 0.0f); v1 *= v1;
                    __nv_bfloat16 h0, h1, l0, l1;
                    split_bf16(v0, h0, l0);
                    split_bf16(v1, h1, l1);
                    size_t o = (size_t)(m + 8 * h) * Nst + n;
                    *(__nv_bfloat162*)(outH + o) = __halves2bfloat162(h0, h1);
                    *(__nv_bfloat162*)(outL + o) = __halves2bfloat162(l0, l1);
                }
            } else {
                size_t o0 = (size_t)m * Nst + n;
                size_t o1 = (size_t)(m + 8) * Nst + n;
                *(float2*)(outF + o0) = make_float2(acc[mi][nj][0], acc[mi][nj][1]);
                *(float2*)(outF + o1) = make_float2(acc[mi][nj][2], acc[mi][nj][3]);
            }
        }
    }
}

// ---------------- host ----------------
typedef CUresult (*EncodeFn)(CUtensorMap*, CUtensorMapDataType, cuuint32_t, void*,
                             const cuuint64_t*, const cuuint64_t*, const cuuint32_t*,
                             const cuuint32_t*, CUtensorMapInterleave, CUtensorMapSwizzle,
                             CUtensorMapL2promotion, CUtensorMapFloatOOBfill);

static int mk_map(EncodeFn enc, CUtensorMap* m, void* p, uint64_t Kdim, uint64_t Rows)
{
    cuuint64_t dims[2]    = {Kdim, Rows};
    cuuint64_t strides[1] = {Kdim * 2};
    cuuint32_t box[2]     = {64u, 128u};
    cuuint32_t es[2]      = {1u, 1u};
    CUresult r = enc(m, CU_TENSOR_MAP_DATA_TYPE_BFLOAT16, 2, p, dims, strides, box, es,
                     CU_TENSOR_MAP_INTERLEAVE_NONE, CU_TENSOR_MAP_SWIZZLE_128B,
                     CU_TENSOR_MAP_L2_PROMOTION_L2_128B, CU_TENSOR_MAP_FLOAT_OOB_FILL_NONE);
    return r == CUDA_SUCCESS;
}

extern "C" void kernel_launch(void* const* d_in, const int* in_sizes, int n_in,
                              void* d_out, int out_size)
{
    const float* x      = (const float*)d_in[0];
    const float* w_fc   = (const float*)d_in[1];
    const float* w_proj = (const float*)d_in[2];
    float*       out    = (float*)d_out;

    static EncodeFn enc = nullptr;
    static void *xh, *xl, *wfh, *wfl, *wph, *wpl, *hh, *hl;
    if (!enc) {
        cudaDriverEntryPointQueryResult st;
        void* fn = nullptr;
        cudaGetDriverEntryPointByVersion("cuTensorMapEncodeTiled", &fn, 12000,
                                         cudaEnableDefault, &st);
        enc = (EncodeFn)fn;
        cudaGetSymbolAddress(&xh,  g_xh);  cudaGetSymbolAddress(&xl,  g_xl);
        cudaGetSymbolAddress(&wfh, g_wfh); cudaGetSymbolAddress(&wfl, g_wfl);
        cudaGetSymbolAddress(&wph, g_wph); cudaGetSymbolAddress(&wpl, g_wpl);
        cudaGetSymbolAddress(&hh,  g_hh);  cudaGetSymbolAddress(&hl,  g_hl);
        cudaFuncSetAttribute(gemm_mma<1>, cudaFuncAttributeMaxDynamicSharedMemorySize, GSMEM_SZ);
        cudaFuncSetAttribute(gemm_mma<0>, cudaFuncAttributeMaxDynamicSharedMemorySize, GSMEM_SZ);
    }
    if (!enc) return;   // encoder unavailable: output stays poisoned -> loud failure

    CUtensorMap tXh, tXl, tFh, tFl, tHh, tHl, tPh, tPl;
    int ok = 1;
    ok &= mk_map(enc, &tXh, xh,  DIM,    M_DIM);
    ok &= mk_map(enc, &tXl, xl,  DIM,    M_DIM);
    ok &= mk_map(enc, &tFh, wfh, DIM,    HIDDEN);
    ok &= mk_map(enc, &tFl, wfl, DIM,    HIDDEN);
    ok &= mk_map(enc, &tHh, hh,  HIDDEN, M_DIM);
    ok &= mk_map(enc, &tHl, hl,  HIDDEN, M_DIM);
    ok &= mk_map(enc, &tPh, wph, HIDDEN, DIM);
    ok &= mk_map(enc, &tPl, wpl, HIDDEN, DIM);
    if (!ok) return;

    // 1) quantize + split weights; split x
    {
        int blocks = (HIDDEN * DIM) / 64;
        quant_split_kernel<<<blocks * 32 / 256, 256>>>(w_fc,   (__nv_bfloat16*)wfh, (__nv_bfloat16*)wfl, blocks);
        quant_split_kernel<<<blocks * 32 / 256, 256>>>(w_proj, (__nv_bfloat16*)wph, (__nv_bfloat16*)wpl, blocks);
        int n4 = (M_DIM * DIM) / 4;
        split_kernel<<<n4 / 256, 256>>>((const float4*)x, (uint2*)xh, (uint2*)xl, n4);
    }
    // 2) H = relusq(x @ w_fc^T) -> bf16 hi/lo planes
    {
        dim3 grid(HIDDEN / 128, M_DIM / 128);   // (64, 64)
        gemm_mma<1><<<grid, 256, GSMEM_SZ>>>(tXh, tXl, tFh, tFl,
                                             nullptr, (__nv_bfloat16*)hh, (__nv_bfloat16*)hl,
                                             HIDDEN, DIM);
    }
    // 3) out = H @ w_proj^T  (fp32)
    {
        dim3 grid(DIM / 128, M_DIM / 128);      // (16, 64)
        gemm_mma<0><<<grid, 256, GSMEM_SZ>>>(tHh, tHl, tPh, tPl,
                                             out, nullptr, nullptr,
                                             DIM, HIDDEN);
    }
}

// round 9
// speedup vs baseline: 4.4673x; 1.3433x over previous
#include <cuda_runtime.h>
#include <cuda.h>
#include <cuda_fp16.h>
#include <math_constants.h>
#include <cstdint>

#define M_DIM  8192
#define DIM    2048
#define HIDDEN 8192

// Device scratch (allocation-free rule). fp16 planes:
//   x  : hi + lo ;  w_fc, w_proj : single (quantized) plane
//   H  : hi + lo (written by GEMM1 epilogue)
__device__ __align__(1024) __half g_xh [(size_t)M_DIM * DIM];
__device__ __align__(1024) __half g_xl [(size_t)M_DIM * DIM];
__device__ __align__(1024) __half g_wf [(size_t)HIDDEN * DIM];
__device__ __align__(1024) __half g_wp [(size_t)DIM * HIDDEN];
__device__ __align__(1024) __half g_hh [(size_t)M_DIM * HIDDEN];
__device__ __align__(1024) __half g_hl [(size_t)M_DIM * HIDDEN];

__constant__ float c_shrinks[16] = {
    0.40f, 0.44f, 0.48f, 0.52f, 0.56f, 0.60f, 0.64f, 0.68f,
    0.72f, 0.76f, 0.80f, 0.84f, 0.88f, 0.92f, 0.96f, 1.00f
};

// ---------------- PTX helpers (baseline ISA only) ----------------
__device__ __forceinline__ uint32_t smem_u32(const void* p) {
    uint32_t a;
    asm("{ .reg .u64 t; cvta.to.shared.u64 t, %1; cvt.u32.u64 %0, t; }" : "=r"(a) : "l"(p));
    return a;
}
#define MBARRIER_INIT(a, c) \
    asm volatile("mbarrier.init.shared.b64 [%0], %1;" :: "r"(a), "r"(c) : "memory")
#define MBARRIER_EXPECT_TX(a, b) \
    asm volatile("mbarrier.arrive.expect_tx.shared.b64 _, [%0], %1;" :: "r"(a), "r"(b) : "memory")

__device__ __forceinline__ int mbar_try(uint32_t a, uint32_t ph) {
    uint32_t d;
    asm volatile("{\n\t.reg .pred p;\n\t"
        "mbarrier.try_wait.parity.acquire.cta.shared::cta.b64 p, [%1], %2, 0x989680;\n\t"
        "selp.b32 %0, 1, 0, p;\n\t}" : "=r"(d) : "r"(a), "r"(ph) : "memory");
    return d;
}
// Bounded wait: converts a never-arriving barrier into a clean trap, not a hang.
#define MBARRIER_WAIT(a, ph) do { \
    uint32_t _m = (a), _p = (uint32_t)(ph); long _i = 0; \
    while (!mbar_try(_m, _p)) { if (++_i > (1L << 22)) __trap(); } \
} while (0)

#define TMA2D(sm, mp, cx, cy, mb) \
    asm volatile("cp.async.bulk.tensor.2d.shared::cta.global.tile.mbarrier::complete_tx::bytes " \
                 "[%0], [%1, {%2, %3}], [%4];" \
                 :: "r"(sm), "l"(mp), "r"(cx), "r"(cy), "r"(mb) : "memory")

#define LDSM_X4(r0, r1, r2, r3, addr) \
    asm volatile("ldmatrix.sync.aligned.m8n8.x4.shared.b16 {%0,%1,%2,%3}, [%4];" \
        : "=r"(r0), "=r"(r1), "=r"(r2), "=r"(r3) : "r"(addr))

__device__ __forceinline__ void mma_f16(float* c, const uint32_t* a, const uint32_t* b) {
    asm volatile(
        "mma.sync.aligned.m16n8k16.row.col.f32.f16.f16.f32 "
        "{%0,%1,%2,%3}, {%4,%5,%6,%7}, {%8,%9}, {%0,%1,%2,%3};"
        : "+f"(c[0]), "+f"(c[1]), "+f"(c[2]), "+f"(c[3])
        : "r"(a[0]), "r"(a[1]), "r"(a[2]), "r"(a[3]), "r"(b[0]), "r"(b[1]));
}

__device__ __forceinline__ uint32_t sw128(uint32_t off) {
    return off ^ ((off >> 3) & 0x70);
}

// ---------------- prep kernels ----------------
__device__ __forceinline__ void split_f16(float v, __half& h, __half& l) {
    h = __float2half_rn(v);
    l = __float2half_rn(v - __half2float(h));
}

// Block-64 symmetric int5 MSE quant-dequant -> single fp16 plane.
__global__ void quant_f16_kernel(const float* __restrict__ W,
                                 __half* __restrict__ WQ,
                                 int total_blocks)
{
    int warp = (blockIdx.x * blockDim.x + threadIdx.x) >> 5;
    int lane = threadIdx.x & 31;
    if (warp >= total_blocks) return;
    size_t base = (size_t)warp * 64;
    float v0 = W[base + lane];
    float v1 = W[base + 32 + lane];
    float am = fmaxf(fabsf(v0), fabsf(v1));
    #pragma unroll
    for (int o = 16; o > 0; o >>= 1)
        am = fmaxf(am, __shfl_xor_sync(0xffffffffu, am, o));
    float bscale = fmaxf(am, 1e-8f) / 15.0f;
    float best_err = CUDART_INF_F, best_scale = bscale;
    #pragma unroll
    for (int i = 0; i < 16; i++) {
        float scale = bscale * c_shrinks[i];
        float q0 = fminf(fmaxf(rintf(v0 / scale), -15.0f), 15.0f);
        float q1 = fminf(fmaxf(rintf(v1 / scale), -15.0f), 15.0f);
        float d0 = q0 * scale - v0, d1 = q1 * scale - v1;
        float e = d0 * d0 + d1 * d1;
        #pragma unroll
        for (int o = 16; o > 0; o >>= 1)
            e += __shfl_xor_sync(0xffffffffu, e, o);
        if (e < best_err) { best_err = e; best_scale = scale; }
    }
    float q0 = fminf(fmaxf(rintf(v0 / best_scale), -15.0f), 15.0f);
    float q1 = fminf(fmaxf(rintf(v1 / best_scale), -15.0f), 15.0f);
    WQ[base + lane]      = __float2half_rn(q0 * best_scale);
    WQ[base + 32 + lane] = __float2half_rn(q1 * best_scale);
}

__global__ void split_kernel(const float4* __restrict__ in,
                             uint2* __restrict__ hi, uint2* __restrict__ lo, int n4)
{
    int i = blockIdx.x * blockDim.x + threadIdx.x;
    if (i >= n4) return;
    float4 v = in[i];
    __half h0, h1, h2, h3, l0, l1, l2, l3;
    split_f16(v.x, h0, l0); split_f16(v.y, h1, l1);
    split_f16(v.z, h2, l2); split_f16(v.w, h3, l3);
    __half2 ha = __halves2half2(h0, h1), hb = __halves2half2(h2, h3);
    __half2 la = __halves2half2(l0, l1), lb = __halves2half2(l2, l3);
    hi[i] = make_uint2(*(uint32_t*)&ha, *(uint32_t*)&hb);
    lo[i] = make_uint2(*(uint32_t*)&la, *(uint32_t*)&lb);
}

// ---------------- mma.sync GEMM ----------------
// C[M,N] = A[M,K]*B[N,K]^T.  A = Ah + Al (fp16 planes), B = Bh (fp16).
// D = Ah*Bh + Al*Bh  (2 MMAs per k-step).
// CTA 128x128, K-chunk 64, 8 warps (2x4), warp tile 64x32.
// 4-stage TMA pipeline, 48KB/stage. MODE1: relusq + fp16-split out; MODE0: fp32.
#define OFF_AH 0
#define OFF_AL 16384
#define OFF_BH 32768
#define STAGE_BYTES 49152
#define NSTAGE 4
#define GSMEM_SZ (2048 + NSTAGE * STAGE_BYTES)

template<int MODE>
__global__ void __launch_bounds__(256, 1) gemm_mma(
    const __grid_constant__ CUtensorMap tAh,
    const __grid_constant__ CUtensorMap tAl,
    const __grid_constant__ CUtensorMap tBh,
    float* __restrict__ outF,
    __half* __restrict__ outH,
    __half* __restrict__ outL,
    int Nst, int K_total)
{
    extern __shared__ char smem_raw[];
    uint32_t sb = smem_u32(smem_raw);
    uint32_t ab = (sb + 1023u) & ~1023u;
    const uint32_t ST0 = ab + 1024;

    int tid  = threadIdx.x;
    int lane = tid & 31;
    int warp = tid >> 5;
    int wm = warp & 1;          // 0..1 -> 64-row slab
    int wn = warp >> 1;         // 0..3 -> 32-col slab
    int m0 = blockIdx.y * 128;
    int n0 = blockIdx.x * 128;

    if (tid == 0) {
        #pragma unroll
        for (int s = 0; s < NSTAGE; s++) MBARRIER_INIT(ab + s * 8, 1);
    }
    __syncthreads();

    const int NC = K_total / 64;

    // Prologue: fill all stages
    if (tid == 0) {
        #pragma unroll
        for (int c = 0; c < NSTAGE; c++) {
            uint32_t st = ST0 + c * STAGE_BYTES;
            uint32_t mb = ab + c * 8;
            MBARRIER_EXPECT_TX(mb, STAGE_BYTES);
            int k0 = c * 64;
            TMA2D(st + OFF_AH, &tAh, k0, m0, mb);
            TMA2D(st + OFF_AL, &tAl, k0, m0, mb);
            TMA2D(st + OFF_BH, &tBh, k0, n0, mb);
        }
    }

    // ldmatrix per-lane patterns (non-trans, K-contiguous 128B rows)
    int a_r = (lane < 16) ? lane : (lane - 16);
    int a_k = (lane < 16) ? 0 : 8;
    int g = lane >> 3;
    int b_r = (lane & 7) + ((g & 2) << 2);
    int b_k = (g & 1) << 3;

    float acc[4][4][4];
    #pragma unroll
    for (int i = 0; i < 4; i++)
        #pragma unroll
        for (int j = 0; j < 4; j++)
            #pragma unroll
            for (int q = 0; q < 4; q++)
                acc[i][j][q] = 0.0f;

    int phase[NSTAGE] = {0, 0, 0, 0};

    for (int c = 0; c < NC; c++) {
        int s = c & (NSTAGE - 1);
        MBARRIER_WAIT(ab + s * 8, phase[s]);
        phase[s] ^= 1;
        uint32_t st = ST0 + s * STAGE_BYTES;

        #pragma unroll
        for (int ks = 0; ks < 4; ks++) {
            int k0 = ks * 16;
            uint32_t Ah[4][4], Al[4][4], Bh[2][4];
            #pragma unroll
            for (int mi = 0; mi < 4; mi++) {
                uint32_t off = (uint32_t)((wm * 64 + mi * 16 + a_r) * 128 + (k0 + a_k) * 2);
                off = sw128(off);
                LDSM_X4(Ah[mi][0], Ah[mi][1], Ah[mi][2], Ah[mi][3], st + OFF_AH + off);
                LDSM_X4(Al[mi][0], Al[mi][1], Al[mi][2], Al[mi][3], st + OFF_AL + off);
            }
            #pragma unroll
            for (int ni = 0; ni < 2; ni++) {
                uint32_t off = (uint32_t)((wn * 32 + ni * 16 + b_r) * 128 + (k0 + b_k) * 2);
                off = sw128(off);
                LDSM_X4(Bh[ni][0], Bh[ni][1], Bh[ni][2], Bh[ni][3], st + OFF_BH + off);
            }
            #pragma unroll
            for (int mi = 0; mi < 4; mi++) {
                #pragma unroll
                for (int nj = 0; nj < 4; nj++) {
                    const uint32_t* bh = &Bh[nj >> 1][(nj & 1) * 2];
                    mma_f16(acc[mi][nj], Ah[mi], bh);
                    mma_f16(acc[mi][nj], Al[mi], bh);
                }
            }
        }
        __syncthreads();          // all warps done reading stage s
        if (tid == 0 && c + NSTAGE < NC) {
            uint32_t mb = ab + s * 8;
            MBARRIER_EXPECT_TX(mb, STAGE_BYTES);
            int k0 = (c + NSTAGE) * 64;
            TMA2D(st + OFF_AH, &tAh, k0, m0, mb);
            TMA2D(st + OFF_AL, &tAl, k0, m0, mb);
            TMA2D(st + OFF_BH, &tBh, k0, n0, mb);
        }
    }

    // Epilogue straight from registers.
    int mbase = m0 + wm * 64 + (lane >> 2);
    int nbase = n0 + wn * 32 + (lane & 3) * 2;
    #pragma unroll
    for (int mi = 0; mi < 4; mi++) {
        #pragma unroll
        for (int nj = 0; nj < 4; nj++) {
            int m = mbase + mi * 16;
            int n = nbase + nj * 8;
            if (MODE == 1) {
                #pragma unroll
                for (int h = 0; h < 2; h++) {      // h=0: row m; h=1: row m+8
                    float v0 = acc[mi][nj][2 * h + 0];
                    float v1 = acc[mi][nj][2 * h + 1];
                    v0 = fmaxf(v0, 0.0f); v0 *= v0;
                    v1 = fmaxf(v1, 0.0f); v1 *= v1;
                    __half h0, h1, l0, l1;
                    split_f16(v0, h0, l0);
                    split_f16(v1, h1, l1);
                    size_t o = (size_t)(m + 8 * h) * Nst + n;
                    *(__half2*)(outH + o) = __halves2half2(h0, h1);
                    *(__half2*)(outL + o) = __halves2half2(l0, l1);
                }
            } else {
                size_t o0 = (size_t)m * Nst + n;
                size_t o1 = (size_t)(m + 8) * Nst + n;
                *(float2*)(outF + o0) = make_float2(acc[mi][nj][0], acc[mi][nj][1]);
                *(float2*)(outF + o1) = make_float2(acc[mi][nj][2], acc[mi][nj][3]);
            }
        }
    }
}

// ---------------- host ----------------
typedef CUresult (*EncodeFn)(CUtensorMap*, CUtensorMapDataType, cuuint32_t, void*,
                             const cuuint64_t*, const cuuint64_t*, const cuuint32_t*,
                             const cuuint32_t*, CUtensorMapInterleave, CUtensorMapSwizzle,
                             CUtensorMapL2promotion, CUtensorMapFloatOOBfill);

static int mk_map(EncodeFn enc, CUtensorMap* m, void* p, uint64_t Kdim, uint64_t Rows)
{
    cuuint64_t dims[2]    = {Kdim, Rows};
    cuuint64_t strides[1] = {Kdim * 2};
    cuuint32_t box[2]     = {64u, 128u};
    cuuint32_t es[2]      = {1u, 1u};
    CUresult r = enc(m, CU_TENSOR_MAP_DATA_TYPE_FLOAT16, 2, p, dims, strides, box, es,
                     CU_TENSOR_MAP_INTERLEAVE_NONE, CU_TENSOR_MAP_SWIZZLE_128B,
                     CU_TENSOR_MAP_L2_PROMOTION_L2_128B, CU_TENSOR_MAP_FLOAT_OOB_FILL_NONE);
    return r == CUDA_SUCCESS;
}

extern "C" void kernel_launch(void* const* d_in, const int* in_sizes, int n_in,
                              void* d_out, int out_size)
{
    const float* x      = (const float*)d_in[0];
    const float* w_fc   = (const float*)d_in[1];
    const float* w_proj = (const float*)d_in[2];
    float*       out    = (float*)d_out;

    static EncodeFn enc = nullptr;
    static void *xh, *xl, *wf, *wp, *hh, *hl;
    if (!enc) {
        cudaDriverEntryPointQueryResult st;
        void* fn = nullptr;
        cudaGetDriverEntryPointByVersion("cuTensorMapEncodeTiled", &fn, 12000,
                                         cudaEnableDefault, &st);
        enc = (EncodeFn)fn;
        cudaGetSymbolAddress(&xh, g_xh); cudaGetSymbolAddress(&xl, g_xl);
        cudaGetSymbolAddress(&wf, g_wf); cudaGetSymbolAddress(&wp, g_wp);
        cudaGetSymbolAddress(&hh, g_hh); cudaGetSymbolAddress(&hl, g_hl);
        cudaFuncSetAttribute(gemm_mma<1>, cudaFuncAttributeMaxDynamicSharedMemorySize, GSMEM_SZ);
        cudaFuncSetAttribute(gemm_mma<0>, cudaFuncAttributeMaxDynamicSharedMemorySize, GSMEM_SZ);
    }
    if (!enc) return;   // encoder unavailable: output stays poisoned -> loud failure

    CUtensorMap tXh, tXl, tF, tHh, tHl, tP;
    int ok = 1;
    ok &= mk_map(enc, &tXh, xh, DIM,    M_DIM);
    ok &= mk_map(enc, &tXl, xl, DIM,    M_DIM);
    ok &= mk_map(enc, &tF,  wf, DIM,    HIDDEN);
    ok &= mk_map(enc, &tHh, hh, HIDDEN, M_DIM);
    ok &= mk_map(enc, &tHl, hl, HIDDEN, M_DIM);
    ok &= mk_map(enc, &tP,  wp, HIDDEN, DIM);
    if (!ok) return;

    // 1) quantize weights -> fp16 plane; split x -> fp16 hi/lo
    {
        int blocks = (HIDDEN * DIM) / 64;
        quant_f16_kernel<<<blocks * 32 / 256, 256>>>(w_fc,   (__half*)wf, blocks);
        quant_f16_kernel<<<blocks * 32 / 256, 256>>>(w_proj, (__half*)wp, blocks);
        int n4 = (M_DIM * DIM) / 4;
        split_kernel<<<n4 / 256, 256>>>((const float4*)x, (uint2*)xh, (uint2*)xl, n4);
    }
    // 2) H = relusq(x @ w_fc^T) -> fp16 hi/lo planes
    {
        dim3 grid(HIDDEN / 128, M_DIM / 128);   // (64, 64)
        gemm_mma<1><<<grid, 256, GSMEM_SZ>>>(tXh, tXl, tF,
                                             nullptr, (__half*)hh, (__half*)hl,
                                             HIDDEN, DIM);
    }
    // 3) out = H @ w_proj^T  (fp32)
    {
        dim3 grid(DIM / 128, M_DIM / 128);      // (16, 64)
        gemm_mma<0><<<grid, 256, GSMEM_SZ>>>(tHh, tHl, tP,
                                             out, nullptr, nullptr,
                                             DIM, HIDDEN);
    }
}